// round 8
// baseline (speedup 1.0000x reference)
#include <cuda_runtime.h>
#include <cstdint>

// Fixed shapes
#define HH 256
#define WW 512
#define HW (HH * WW)                 // floats per plane
#define HW4 (HW / 4)                 // 32768 float4/plane
#define W4 (WW / 4)                  // 128 float4/row
#define NSTUFF 11
#define STUFF4 (NSTUFF * HW4)
#define TPB 256
#define ITEMS 8                      // float4 per thread per chunk
#define F4_PER_CHUNK (TPB * ITEMS)   // 2048 float4 = 32 KB = 16 rows
#define CHUNK_BYTES (F4_PER_CHUNK * 16)
#define ROWS_PER_CHUNK 16
#define STUFF_CHUNKS (STUFF4 / F4_PER_CHUNK)     // 176
#define CHUNKS_PER_PLANE (HW4 / F4_PER_CHUNK)    // 16
#define NBOX 128
#define NCHUNKS (NBOX * CHUNKS_PER_PLANE)        // 2048

__device__ __forceinline__ uint32_t smem_u32(const void* p) {
    return (uint32_t)__cvta_generic_to_shared(p);
}

// Shared deterministic box resolution — MUST be identical on both CTA roles.
__device__ __forceinline__ void resolve_box(
    const int* cls, const float* boxes, int n,
    int& x0, int& y0, int& x1, int& y1, int& m)
{
    const int c = __ldg(cls + n);
    x0 = 0; y0 = 0; x1 = 0; y1 = 0; m = -1;
    if (c != 0) {
        const float* bb = boxes + n * 5;
        x0 = (int)floorf(__ldg(bb + 1) * 0.25f);
        y0 = (int)floorf(__ldg(bb + 2) * 0.25f);
        x1 = (int)(rintf(__ldg(bb + 3) * 0.25f) + 1.0f);  // half-even = jnp.round
        y1 = (int)(rintf(__ldg(bb + 4) * 0.25f) + 1.0f);
        if (x1 > x0 && y1 > y0 && x1 > 0 && x0 < WW && y1 > 0 && y0 < HH)
            m = (c + 10 > 18) ? 18 : c + 10;
    }
}

__global__ __launch_bounds__(TPB) void seg_term_kernel(
    const int*    __restrict__ cls,     // [128]
    const float*  __restrict__ seg,     // [19*HW]
    const float*  __restrict__ boxes,   // [128*5]
    float*        __restrict__ out)
{
    __shared__ __align__(128) float4 zbuf[F4_PER_CHUNK];   // 32 KB of zeros (TMA source)

    const int b   = blockIdx.x;
    const int tid = threadIdx.x;
    const float4 z = make_float4(0.f, 0.f, 0.f, 0.f);

    if (b < NBOX) {
        // ================= zero-plane CTA (scheduled first) =================
        const int n = b;
        // Zero the TMA source buffer (overlaps the dependent box-load chain).
        #pragma unroll
        for (int k = 0; k < ITEMS; k++) zbuf[tid + k * TPB] = z;

        int x0, y0, x1, y1, m;
        resolve_box(cls, boxes, n, x0, y0, x1, y1, m);

        __syncthreads();

        if (tid == 0) {
            asm volatile("fence.proxy.async.shared::cta;" ::: "memory");
            float4* oplane = reinterpret_cast<float4*>(out) + STUFF4 + n * HW4;
            const uint32_t src = smem_u32(zbuf);
            #pragma unroll
            for (int blk = 0; blk < CHUNKS_PER_PLANE; blk++) {
                const int r0 = blk * ROWS_PER_CHUNK;
                const bool inter = (m >= 0) && (y1 > r0) && (y0 < r0 + ROWS_PER_CHUNK);
                if (!inter) {
                    asm volatile(
                        "cp.async.bulk.global.shared::cta.bulk_group [%0], [%1], %2;"
                        :: "l"(oplane + blk * F4_PER_CHUNK), "r"(src), "n"(CHUNK_BYTES)
                        : "memory");
                }
            }
            asm volatile("cp.async.bulk.commit_group;" ::: "memory");
            asm volatile("cp.async.bulk.wait_group 0;" ::: "memory");
        }
        return;
    }

    if (b < NBOX + STUFF_CHUNKS) {
        // ================= stuff copy chunk (R3 proven path) =================
        const int ch = b - NBOX;
        const float4* s4 = reinterpret_cast<const float4*>(seg) + ch * F4_PER_CHUNK;
        float4*       o4 = reinterpret_cast<float4*>(out)       + ch * F4_PER_CHUNK;
        float4 v[ITEMS];
        #pragma unroll
        for (int k = 0; k < ITEMS; k++) v[k] = s4[tid + k * TPB];
        #pragma unroll
        for (int k = 0; k < ITEMS; k++) o4[tid + k * TPB] = v[k];
        return;
    }

    // ================= gather-chunk CTA =================
    const int ic  = b - NBOX - STUFF_CHUNKS;     // 0..2047
    const int n   = ic >> 4;
    const int blk = ic & (CHUNKS_PER_PLANE - 1);
    const int r0  = blk * ROWS_PER_CHUNK;

    int x0, y0, x1, y1, m;
    resolve_box(cls, boxes, n, x0, y0, x1, y1, m);

    const bool inter = (m >= 0) && (y1 > r0) && (y0 < r0 + ROWS_PER_CHUNK);
    if (!inter) return;                          // covered by zero-plane CTA

    float4* o4 = reinterpret_cast<float4*>(out) + STUFF4 + n * HW4 + blk * F4_PER_CHUNK;
    const float4* s4 = reinterpret_cast<const float4*>(seg) + m * HW4 + blk * F4_PER_CHUNK;

    const int x = (tid & (W4 - 1)) << 2;         // first scalar col of this float4
    const bool col_full = (x >= x0) && ((x + 3) < x1);
    const bool col_edge = !col_full && ((x + 3) >= x0) && (x < x1);

    float4 v[ITEMS];
    #pragma unroll
    for (int k = 0; k < ITEMS; k++) {
        const int idx = tid + k * TPB;
        const int y   = r0 + (idx >> 7);
        v[k] = z;
        if (y >= y0 && y < y1) {
            if (col_full) {
                v[k] = s4[idx];
            } else if (col_edge) {
                const float* sr = reinterpret_cast<const float*>(s4 + idx);
                float vv[4];
                #pragma unroll
                for (int j = 0; j < 4; j++) {
                    const int xx = x + j;
                    vv[j] = (xx >= x0 && xx < x1) ? sr[j] : 0.f;
                }
                v[k] = make_float4(vv[0], vv[1], vv[2], vv[3]);
            }
        }
    }
    #pragma unroll
    for (int k = 0; k < ITEMS; k++) o4[tid + k * TPB] = v[k];
}

extern "C" void kernel_launch(void* const* d_in, const int* in_sizes, int n_in,
                              void* d_out, int out_size)
{
    const int*   cls   = (const int*)d_in[0];
    const float* seg   = (const float*)d_in[1];
    const float* boxes = (const float*)d_in[2];
    float* out = (float*)d_out;

    const int blocks = NBOX + STUFF_CHUNKS + NCHUNKS;   // 128 + 176 + 2048 = 2352
    seg_term_kernel<<<blocks, TPB>>>(cls, seg, boxes, out);
}

// round 9
// speedup vs baseline: 1.4056x; 1.4056x over previous
#include <cuda_runtime.h>

// Fixed shapes
#define HH 256
#define WW 512
#define HW (HH * WW)                 // floats per plane
#define HW4 (HW / 4)                 // 32768 float4/plane
#define W4 (WW / 4)                  // 128 float4/row
#define NSTUFF 11
#define STUFF4 (NSTUFF * HW4)
#define TPB 256
#define ITEMS 8                      // float4 per thread per chunk
#define F4C (TPB * ITEMS)            // 2048 float4 = 16 rows per chunk
#define ROWS_PER_CHUNK 16
#define STUFF_CHUNKS (STUFF4 / F4C)          // 176
#define CHUNKS_PER_PLANE (HW4 / F4C)         // 16
#define NBOX 128
#define STUFF_CTAS (STUFF_CHUNKS / 2)        // 88  (2 chunks per CTA)
#define PLANE_CTAS (CHUNKS_PER_PLANE / 2)    // 8 CTAs per plane
#define INST_CTAS (NBOX * PLANE_CTAS)        // 1024

__global__ __launch_bounds__(TPB) void seg_term_kernel(
    const int*    __restrict__ cls,     // [128]
    const float*  __restrict__ seg,     // [19*HW]
    const float*  __restrict__ boxes,   // [128*5]
    float*        __restrict__ out)
{
    const int b   = blockIdx.x;
    const int tid = threadIdx.x;
    const float4 z = make_float4(0.f, 0.f, 0.f, 0.f);

    if (b < STUFF_CTAS) {
        // ---- stuff copy: 2 chunks, each 8 batched loads then 8 streaming stores ----
        const float4* s4 = reinterpret_cast<const float4*>(seg) + b * 2 * F4C;
        float4*       o4 = reinterpret_cast<float4*>(out)       + b * 2 * F4C;
        #pragma unroll
        for (int h = 0; h < 2; h++) {
            float4 v[ITEMS];
            #pragma unroll
            for (int k = 0; k < ITEMS; k++) v[k] = s4[h * F4C + tid + k * TPB];
            #pragma unroll
            for (int k = 0; k < ITEMS; k++) __stcs(&o4[h * F4C + tid + k * TPB], v[k]);
        }
        return;
    }

    // ---- instance region: each CTA owns 2 consecutive chunks (32 rows) of ONE plane ----
    const int ic = b - STUFF_CTAS;               // 0..1023
    const int n  = ic >> 3;                      // plane (8 CTAs/plane)
    const int q  = ic & (PLANE_CTAS - 1);        // which pair of chunks

    float4* oplane = reinterpret_cast<float4*>(out) + STUFF4 + n * HW4;

    // Resolve box ONCE per 2 chunks
    const int c = __ldg(cls + n);
    int x0 = 0, y0 = 0, x1 = 0, y1 = 0, m = -1;
    if (c != 0) {
        const float* bb = boxes + n * 5;
        x0 = (int)floorf(__ldg(bb + 1) * 0.25f);
        y0 = (int)floorf(__ldg(bb + 2) * 0.25f);
        x1 = (int)(rintf(__ldg(bb + 3) * 0.25f) + 1.0f);  // half-even = jnp.round
        y1 = (int)(rintf(__ldg(bb + 4) * 0.25f) + 1.0f);
        if (x1 > x0 && y1 > y0 && x1 > 0 && x0 < WW && y1 > 0 && y0 < HH)
            m = (c + 10 > 18) ? 18 : c + 10;
    }

    // Loop-invariant column classification
    const int x = (tid & (W4 - 1)) << 2;
    const bool col_full = (m >= 0) && (x >= x0) && ((x + 3) < x1);
    const bool col_edge = (m >= 0) && !col_full && ((x + 3) >= x0) && (x < x1);
    const float4* splane = (m >= 0)
        ? reinterpret_cast<const float4*>(seg) + m * HW4 : nullptr;

    #pragma unroll
    for (int h = 0; h < 2; h++) {
        const int blk = q * 2 + h;
        const int r0  = blk * ROWS_PER_CHUNK;
        float4* o4 = oplane + blk * F4C;

        const bool inter = (m >= 0) && (y1 > r0) && (y0 < r0 + ROWS_PER_CHUNK);

        if (!inter) {
            // zero burst
            #pragma unroll
            for (int k = 0; k < ITEMS; k++) __stcs(&o4[tid + k * TPB], z);
            continue;
        }

        const float4* s4 = splane + blk * F4C;
        float4 v[ITEMS];
        #pragma unroll
        for (int k = 0; k < ITEMS; k++) {
            const int idx = tid + k * TPB;
            const int y   = r0 + (idx >> 7);
            v[k] = z;
            if (y >= y0 && y < y1) {
                if (col_full) {
                    v[k] = s4[idx];
                } else if (col_edge) {
                    const float* sr = reinterpret_cast<const float*>(s4 + idx);
                    float vv[4];
                    #pragma unroll
                    for (int j = 0; j < 4; j++) {
                        const int xx = x + j;
                        vv[j] = (xx >= x0 && xx < x1) ? sr[j] : 0.f;
                    }
                    v[k] = make_float4(vv[0], vv[1], vv[2], vv[3]);
                }
            }
        }
        #pragma unroll
        for (int k = 0; k < ITEMS; k++) __stcs(&o4[tid + k * TPB], v[k]);
    }
}

extern "C" void kernel_launch(void* const* d_in, const int* in_sizes, int n_in,
                              void* d_out, int out_size)
{
    const int*   cls   = (const int*)d_in[0];
    const float* seg   = (const float*)d_in[1];
    const float* boxes = (const float*)d_in[2];
    float* out = (float*)d_out;

    seg_term_kernel<<<STUFF_CTAS + INST_CTAS, TPB>>>(cls, seg, boxes, out);  // 1112 CTAs
}